// round 3
// baseline (speedup 1.0000x reference)
#include <cuda_runtime.h>

#define MAXN 50000
#define MAXE 800000

// ---------------- scratch (static device globals; no allocation) ----------------
__device__ float g_U[(size_t)MAXN * 256];
__device__ float g_h[(size_t)MAXN * 128];
__device__ float g_as[MAXN * 2];
__device__ float g_ad[MAXN * 2];
__device__ float g_x1a[(size_t)MAXN * 64];
__device__ float g_x1b[(size_t)MAXN * 64];
__device__ float g_x2a[(size_t)MAXN * 64];
__device__ float g_x2b[(size_t)MAXN * 64];
__device__ float g_r2[MAXN * 16];
__device__ float g_g2[MAXN * 16];
__device__ int g_cnt[MAXN];
__device__ int g_off[MAXN + 1];
__device__ int g_cur[MAXN];
__device__ int g_csrc[MAXE];
__device__ int g_cet[MAXE];

__device__ __forceinline__ float lrelu(float v) { return v > 0.f ? v : 0.2f * v; }

// ---------------- CSR build ----------------
__global__ void k_hist(const int* __restrict__ dst, int E, int* __restrict__ cnt) {
    int i = blockIdx.x * blockDim.x + threadIdx.x;
    if (i < E) atomicAdd(&cnt[dst[i]], 1);
}

__global__ void k_scan(const int* __restrict__ cnt, int* __restrict__ off,
                       int* __restrict__ cur, int n) {
    __shared__ int tot[1024];
    int tid = threadIdx.x;
    int chunk = (n + 1023) >> 10;
    int s = tid * chunk;
    int e = min(s + chunk, n);
    int sum = 0;
    for (int i = s; i < e; i++) sum += cnt[i];
    tot[tid] = sum;
    __syncthreads();
    if (tid == 0) {
        int acc = 0;
        for (int i = 0; i < 1024; i++) { int t = tot[i]; tot[i] = acc; acc += t; }
    }
    __syncthreads();
    int acc = tot[tid];
    for (int i = s; i < e; i++) {
        off[i] = acc;
        cur[i] = acc;
        acc += cnt[i];
    }
    if (s < n && e == n) off[n] = acc;
}

__global__ void k_scatter(const int* __restrict__ src, const int* __restrict__ dst,
                          const int* __restrict__ et, int E, int* __restrict__ cur,
                          int* __restrict__ csrc, int* __restrict__ cet) {
    int i = blockIdx.x * blockDim.x + threadIdx.x;
    if (i < E) {
        int d = dst[i];
        int p = atomicAdd(&cur[d], 1);
        csrc[p] = src[i];
        cet[p] = et[i];
    }
}

// ---------------- RGCN aggregation (warp per node) ----------------
// U[n, b*64+c] = sum_r comp[r,b] * (sum_{e: dst=n, et=r} x[src[e]][c]) / max(cnt[n,r],1)
__global__ __launch_bounds__(128) void k_rgcn_agg(
        const float* __restrict__ x, const int* __restrict__ off,
        const int* __restrict__ csrc, const int* __restrict__ cet,
        const float* __restrict__ comp, float* __restrict__ U, int n) {
    __shared__ float sums[4][8][64];
    __shared__ int cnts[4][8];
    int w = threadIdx.x >> 5, lane = threadIdx.x & 31;
    int node = blockIdx.x * 4 + w;
    if (node >= n) return;
#pragma unroll
    for (int i = lane; i < 512; i += 32) (&sums[w][0][0])[i] = 0.f;
    if (lane < 8) cnts[w][lane] = 0;
    __syncwarp();
    int st = off[node], en = off[node + 1];
    if (st < en) {
        int s = csrc[st], r = cet[st];
        float2 v = *(const float2*)(x + (size_t)s * 64 + 2 * lane);
        for (int e = st; e < en; e++) {
            // prefetch next edge (clamped)
            int e2 = (e + 1 < en) ? e + 1 : e;
            int s2 = csrc[e2], r2 = cet[e2];
            float2 v2 = *(const float2*)(x + (size_t)s2 * 64 + 2 * lane);
            float2* sp = (float2*)&sums[w][r][0];
            float2 c = sp[lane];
            c.x += v.x;
            c.y += v.y;
            sp[lane] = c;
            if (lane == 0) cnts[w][r]++;
            s = s2; r = r2; v = v2;
        }
    }
    __syncwarp();
    float inv[8];
#pragma unroll
    for (int r = 0; r < 8; r++) inv[r] = 1.f / fmaxf((float)cnts[w][r], 1.f);
#pragma unroll
    for (int b = 0; b < 4; b++) {
        float2 acc = {0.f, 0.f};
#pragma unroll
        for (int r = 0; r < 8; r++) {
            float f = comp[r * 4 + b] * inv[r];
            float2 sv = ((float2*)&sums[w][r][0])[lane];
            acc.x += f * sv.x;
            acc.y += f * sv.y;
        }
        ((float2*)(U + (size_t)node * 256 + b * 64))[lane] = acc;
    }
}

// ---------------- generic tiled GEMM: C = [A1|A2] @ [B1;B2] (+bias)(+relu) ----------------
template <int BN, int TN>
__global__ __launch_bounds__(256) void k_gemm(const float* __restrict__ A1, int K1,
                                              const float* __restrict__ A2, int K2,
                                              const float* __restrict__ B1,
                                              const float* __restrict__ B2,
                                              const float* __restrict__ bias,
                                              float* __restrict__ C, int n, int do_relu) {
    constexpr int BM = 128, BK = 32, TM = 8;
    static_assert(BN / TN == 16, "");
    __shared__ float As[BM][BK + 1];
    __shared__ float Bs[BK][BN];
    int tid = threadIdx.x;
    int tx = tid & 15, ty = tid >> 4;
    int row0 = blockIdx.x * BM;
    int K = K1 + K2;
    float acc[TM][TN];
#pragma unroll
    for (int i = 0; i < TM; i++)
#pragma unroll
        for (int j = 0; j < TN; j++) acc[i][j] = 0.f;

    for (int kt = 0; kt < K; kt += BK) {
#pragma unroll
        for (int i = 0; i < (BM * BK) / 256; i++) {
            int idx = tid + i * 256;
            int r = idx >> 5, k = idx & 31;
            int row = row0 + r, gk = kt + k;
            float v = 0.f;
            if (row < n)
                v = (gk < K1) ? A1[(size_t)row * K1 + gk]
                              : A2[(size_t)row * K2 + (gk - K1)];
            As[r][k] = v;
        }
#pragma unroll
        for (int i = 0; i < (BK * BN) / 256; i++) {
            int idx = tid + i * 256;
            int r = idx / BN, c = idx % BN;
            int gk = kt + r;
            Bs[r][c] = (gk < K1) ? B1[(size_t)gk * BN + c]
                                 : B2[(size_t)(gk - K1) * BN + c];
        }
        __syncthreads();
#pragma unroll
        for (int kk = 0; kk < BK; kk++) {
            float a[TM], b[TN];
#pragma unroll
            for (int i = 0; i < TM; i++) a[i] = As[ty * TM + i][kk];
#pragma unroll
            for (int j = 0; j < TN; j++) b[j] = Bs[kk][tx * TN + j];
#pragma unroll
            for (int i = 0; i < TM; i++)
#pragma unroll
                for (int j = 0; j < TN; j++) acc[i][j] += a[i] * b[j];
        }
        __syncthreads();
    }
#pragma unroll
    for (int i = 0; i < TM; i++) {
        int row = row0 + ty * TM + i;
        if (row >= n) continue;
#pragma unroll
        for (int j = 0; j < TN; j++) {
            int c = tx * TN + j;
            float v = acc[i][j];
            if (bias) v += bias[c];
            if (do_relu) v = fmaxf(v, 0.f);
            C[(size_t)row * BN + c] = v;
        }
    }
}

// ---------------- GAT attention coefficients (warp per node) ----------------
template <int C>
__global__ __launch_bounds__(128) void k_attcoef(
        const float* __restrict__ h, const float* __restrict__ att_s,
        const float* __restrict__ att_d, float* __restrict__ as_,
        float* __restrict__ ad_, int n) {
    int w = threadIdx.x >> 5, lane = threadIdx.x & 31;
    int node = blockIdx.x * (blockDim.x >> 5) + w;
    if (node >= n) return;
    const float* hn = h + (size_t)node * 2 * C;
    if (C >= 32) {
        float s0 = 0, s1 = 0, d0 = 0, d1 = 0;
#pragma unroll
        for (int j = 0; j < C / 32; j++) {
            int c = lane + 32 * j;
            float h0 = hn[c], h1 = hn[C + c];
            s0 += h0 * att_s[c];
            s1 += h1 * att_s[C + c];
            d0 += h0 * att_d[c];
            d1 += h1 * att_d[C + c];
        }
#pragma unroll
        for (int o = 16; o; o >>= 1) {
            s0 += __shfl_xor_sync(0xffffffffu, s0, o);
            s1 += __shfl_xor_sync(0xffffffffu, s1, o);
            d0 += __shfl_xor_sync(0xffffffffu, d0, o);
            d1 += __shfl_xor_sync(0xffffffffu, d1, o);
        }
        if (lane == 0) {
            as_[node * 2] = s0;
            as_[node * 2 + 1] = s1;
            ad_[node * 2] = d0;
            ad_[node * 2 + 1] = d1;
        }
    } else {  // C == 16: lane f = lane; head = lane>>4
        float hv = hn[lane];
        float s = hv * att_s[lane];
        float d = hv * att_d[lane];
#pragma unroll
        for (int o = 8; o; o >>= 1) {
            s += __shfl_xor_sync(0xffffffffu, s, o);
            d += __shfl_xor_sync(0xffffffffu, d, o);
        }
        if (lane == 0) { as_[node * 2] = s; ad_[node * 2] = d; }
        if (lane == 16) { as_[node * 2 + 1] = s; ad_[node * 2 + 1] = d; }
    }
}

// ---------------- GAT aggregation, C=64 (warp per node, float4 + pipeline) ----------------
__global__ __launch_bounds__(128) void k_gat_agg64(
        const float* __restrict__ h, const float* __restrict__ as_,
        const float* __restrict__ ad_, const int* __restrict__ off,
        const int* __restrict__ csrc, const float* __restrict__ bias,
        float* __restrict__ out, int n, int do_relu) {
    int w = threadIdx.x >> 5, lane = threadIdx.x & 31;
    int node = blockIdx.x * (blockDim.x >> 5) + w;
    if (node >= n) return;
    float2 adv = ((const float2*)ad_)[node];
    float2 asn = ((const float2*)as_)[node];
    int st = off[node], en = off[node + 1];
    // pass 1: per-head max (self loop included), lane-parallel
    float m0 = lrelu(asn.x + adv.x);
    float m1 = lrelu(asn.y + adv.y);
    for (int i = st + lane; i < en; i += 32) {
        float2 av = ((const float2*)as_)[csrc[i]];
        m0 = fmaxf(m0, lrelu(av.x + adv.x));
        m1 = fmaxf(m1, lrelu(av.y + adv.y));
    }
#pragma unroll
    for (int o = 16; o; o >>= 1) {
        m0 = fmaxf(m0, __shfl_xor_sync(0xffffffffu, m0, o));
        m1 = fmaxf(m1, __shfl_xor_sync(0xffffffffu, m1, o));
    }
    // pass 2: softmax-weighted accumulation, float4 gather, 1-deep pipeline
    float4 acc = {0.f, 0.f, 0.f, 0.f};
    float sum0 = 0.f, sum1 = 0.f;
    int s = (st < en) ? csrc[st] : node;
    float4 v = ((const float4*)(h + (size_t)s * 128))[lane];
    float2 av = ((const float2*)as_)[s];
    for (int e = st; e <= en; e++) {
        int s2 = (e + 1 < en) ? csrc[e + 1] : node;
        float4 v2 = ((const float4*)(h + (size_t)s2 * 128))[lane];
        float2 av2 = ((const float2*)as_)[s2];
        float w0 = __expf(lrelu(av.x + adv.x) - m0);
        float w1 = __expf(lrelu(av.y + adv.y) - m1);
        sum0 += w0;
        sum1 += w1;
        float ww = (lane < 16) ? w0 : w1;
        acc.x += ww * v.x;
        acc.y += ww * v.y;
        acc.z += ww * v.z;
        acc.w += ww * v.w;
        s = s2; v = v2; av = av2;
    }
    float rn = (lane < 16) ? (1.f / sum0) : (1.f / sum1);
    acc.x *= rn; acc.y *= rn; acc.z *= rn; acc.w *= rn;
    float4 other;
    other.x = __shfl_xor_sync(0xffffffffu, acc.x, 16);
    other.y = __shfl_xor_sync(0xffffffffu, acc.y, 16);
    other.z = __shfl_xor_sync(0xffffffffu, acc.z, 16);
    other.w = __shfl_xor_sync(0xffffffffu, acc.w, 16);
    if (lane < 16) {
        float4 b4 = ((const float4*)bias)[lane];
        float4 o;
        o.x = 0.5f * (acc.x + other.x) + b4.x;
        o.y = 0.5f * (acc.y + other.y) + b4.y;
        o.z = 0.5f * (acc.z + other.z) + b4.z;
        o.w = 0.5f * (acc.w + other.w) + b4.w;
        if (do_relu) {
            o.x = fmaxf(o.x, 0.f); o.y = fmaxf(o.y, 0.f);
            o.z = fmaxf(o.z, 0.f); o.w = fmaxf(o.w, 0.f);
        }
        ((float4*)(out + (size_t)node * 64))[lane] = o;
    }
}

// ---------------- GAT aggregation, C=16 (warp per node) ----------------
__global__ __launch_bounds__(128) void k_gat_agg16(
        const float* __restrict__ h, const float* __restrict__ as_,
        const float* __restrict__ ad_, const int* __restrict__ off,
        const int* __restrict__ csrc, const float* __restrict__ bias,
        float* __restrict__ out, int n) {
    int w = threadIdx.x >> 5, lane = threadIdx.x & 31;
    int node = blockIdx.x * (blockDim.x >> 5) + w;
    if (node >= n) return;
    float2 adv = ((const float2*)ad_)[node];
    float2 asn = ((const float2*)as_)[node];
    int st = off[node], en = off[node + 1];
    float m0 = lrelu(asn.x + adv.x);
    float m1 = lrelu(asn.y + adv.y);
    for (int i = st + lane; i < en; i += 32) {
        float2 av = ((const float2*)as_)[csrc[i]];
        m0 = fmaxf(m0, lrelu(av.x + adv.x));
        m1 = fmaxf(m1, lrelu(av.y + adv.y));
    }
#pragma unroll
    for (int o = 16; o; o >>= 1) {
        m0 = fmaxf(m0, __shfl_xor_sync(0xffffffffu, m0, o));
        m1 = fmaxf(m1, __shfl_xor_sync(0xffffffffu, m1, o));
    }
    float acc = 0.f, sum0 = 0.f, sum1 = 0.f;
    for (int e = st; e <= en; e++) {
        int s = (e < en) ? csrc[e] : node;
        float2 av = ((const float2*)as_)[s];
        float w0 = __expf(lrelu(av.x + adv.x) - m0);
        float w1 = __expf(lrelu(av.y + adv.y) - m1);
        sum0 += w0;
        sum1 += w1;
        acc += ((lane < 16) ? w0 : w1) * h[(size_t)s * 32 + lane];
    }
    float r0 = 1.f / sum0, r1 = 1.f / sum1;
    float other = __shfl_xor_sync(0xffffffffu, acc, 16);
    if (lane < 16) {
        out[(size_t)node * 16 + lane] = 0.5f * (acc * r0 + other * r1) + bias[lane];
    }
}

// ---------------- final combine: tanh(r2 + rowmean(g2)) ----------------
__global__ void k_combine(const float* __restrict__ r2, const float* __restrict__ g2,
                          float* __restrict__ out, int n) {
    int t = blockIdx.x * blockDim.x + threadIdx.x;
    int node = t >> 4, c = t & 15;
    if (node >= n) return;
    float gv = g2[node * 16 + c];
    float s = gv;
#pragma unroll
    for (int o = 8; o; o >>= 1) s += __shfl_xor_sync(0xffffffffu, s, o);
    out[node * 16 + c] = tanhf(r2[node * 16 + c] + s * (1.f / 16.f));
}

// ---------------- host orchestration ----------------
extern "C" void kernel_launch(void* const* d_in, const int* in_sizes, int n_in,
                              void* d_out, int out_size) {
    const float* x = (const float*)d_in[0];
    const int* ei = (const int*)d_in[1];
    const int* et = (const int*)d_in[2];
    int E = in_sizes[2];
    int N = in_sizes[0] / 64;
    if (N > MAXN) N = MAXN;   // fail-soft: never exceed static scratch
    if (E > MAXE) E = MAXE;
    const int* src = ei;
    const int* dst = ei + E;

    const float *rb[3], *rc[3], *rr[3], *rbias[3], *gw[3], *gas[3], *gad[3], *gb[3];
    for (int k = 0; k < 3; k++) {
        int base = 3 + 8 * k;
        rb[k] = (const float*)d_in[base + 0];
        rc[k] = (const float*)d_in[base + 1];
        rr[k] = (const float*)d_in[base + 2];
        rbias[k] = (const float*)d_in[base + 3];
        gw[k] = (const float*)d_in[base + 4];
        gas[k] = (const float*)d_in[base + 5];
        gad[k] = (const float*)d_in[base + 6];
        gb[k] = (const float*)d_in[base + 7];
    }

    void* p;
    float *U, *h, *as_, *ad_, *x1a, *x1b, *x2a, *x2b, *r2, *g2;
    int *cnt, *off, *cur, *csrc, *cet;
    cudaGetSymbolAddress(&p, g_U);   U = (float*)p;
    cudaGetSymbolAddress(&p, g_h);   h = (float*)p;
    cudaGetSymbolAddress(&p, g_as);  as_ = (float*)p;
    cudaGetSymbolAddress(&p, g_ad);  ad_ = (float*)p;
    cudaGetSymbolAddress(&p, g_x1a); x1a = (float*)p;
    cudaGetSymbolAddress(&p, g_x1b); x1b = (float*)p;
    cudaGetSymbolAddress(&p, g_x2a); x2a = (float*)p;
    cudaGetSymbolAddress(&p, g_x2b); x2b = (float*)p;
    cudaGetSymbolAddress(&p, g_r2);  r2 = (float*)p;
    cudaGetSymbolAddress(&p, g_g2);  g2 = (float*)p;
    cudaGetSymbolAddress(&p, g_cnt); cnt = (int*)p;
    cudaGetSymbolAddress(&p, g_off); off = (int*)p;
    cudaGetSymbolAddress(&p, g_cur); cur = (int*)p;
    cudaGetSymbolAddress(&p, g_csrc); csrc = (int*)p;
    cudaGetSymbolAddress(&p, g_cet);  cet = (int*)p;

    // CSR build (by dst)
    cudaMemsetAsync(cnt, 0, (size_t)N * sizeof(int), 0);
    k_hist<<<(E + 255) / 256, 256>>>(dst, E, cnt);
    k_scan<<<1, 1024>>>(cnt, off, cur, N);
    k_scatter<<<(E + 255) / 256, 256>>>(src, dst, et, E, cur, csrc, cet);

    int gWarp = (N + 3) / 4;      // warp-per-node kernels, 128 threads
    int gGemm = (N + 127) / 128;  // BM=128

    // ---- layer 0 ----
    k_rgcn_agg<<<gWarp, 128>>>(x, off, csrc, cet, rc[0], U, N);
    k_gemm<64, 4><<<gGemm, 256>>>(U, 256, x, 64, rb[0], rr[0], rbias[0], x1a, N, 1);

    k_gemm<128, 8><<<gGemm, 256>>>(x, 64, nullptr, 0, gw[0], nullptr, nullptr, h, N, 0);
    k_attcoef<64><<<gWarp, 128>>>(h, gas[0], gad[0], as_, ad_, N);
    k_gat_agg64<<<gWarp, 128>>>(h, as_, ad_, off, csrc, gb[0], x2a, N, 1);

    // ---- layer 1 ----
    k_rgcn_agg<<<gWarp, 128>>>(x1a, off, csrc, cet, rc[1], U, N);
    k_gemm<64, 4><<<gGemm, 256>>>(U, 256, x1a, 64, rb[1], rr[1], rbias[1], x1b, N, 1);

    k_gemm<128, 8><<<gGemm, 256>>>(x2a, 64, nullptr, 0, gw[1], nullptr, nullptr, h, N, 0);
    k_attcoef<64><<<gWarp, 128>>>(h, gas[1], gad[1], as_, ad_, N);
    k_gat_agg64<<<gWarp, 128>>>(h, as_, ad_, off, csrc, gb[1], x2b, N, 1);

    // ---- swap: layer 2 RGCN consumes GAT branch (x2b), GAT consumes RGCN branch (x1b) ----
    k_rgcn_agg<<<gWarp, 128>>>(x2b, off, csrc, cet, rc[2], U, N);
    k_gemm<16, 1><<<gGemm, 256>>>(U, 256, x2b, 64, rb[2], rr[2], rbias[2], r2, N, 0);

    k_gemm<32, 2><<<gGemm, 256>>>(x1b, 64, nullptr, 0, gw[2], nullptr, nullptr, h, N, 0);
    k_attcoef<16><<<gWarp, 128>>>(h, gas[2], gad[2], as_, ad_, N);
    k_gat_agg16<<<gWarp, 128>>>(h, as_, ad_, off, csrc, gb[2], g2, N);

    // ---- combine ----
    k_combine<<<(N * 16 + 255) / 256, 256>>>(r2, g2, (float*)d_out, N);
}